// round 2
// baseline (speedup 1.0000x reference)
#include <cuda_runtime.h>
#include <math.h>

// GlobalFilter: out = irfft2( rfft2(x) * W ), ortho norm, over 14x14 spatial grid.
// Formulated as: row-DFT (u=0..7) -> per-u circular convolution in j with
// precomputed kernel k_u (absorbs fwd-v, pointwise W, inv-v) -> hermitian
// inverse row-DFT.  All fp32, twiddles generated in double.

#define A14 14
#define NFREQ 8            // rfft half-spectrum along v
#define CDIM 768
#define BDIM 256
#define CH 16              // channels per CTA
#define NTHREADS 128       // CH * 8 u-slots

// Precomputed per-channel convolution kernels: k[u][t][c], u=0..7, t=0..13.
__device__ float2 g_k[NFREQ * A14 * CDIM];   // 688 KB
__device__ float  g_cosT[A14];
__device__ float  g_sinT[A14];

// ---------------------------------------------------------------------------
// Prep: k_u[t] = W~[u,0] + (-1)^t W~[u,7]
//              + sum_{v=1..6} [ W[u,v] w^{vt} + conj(W[(14-u)%14,v]) w^{-vt} ]
// with W~[u,v] = (W[u,v] + conj(W[(14-u)%14,v]))/2 for v in {0,7}
// (C2R DC/Nyquist real-projection), all divided by 196 (ortho^2).
// ---------------------------------------------------------------------------
__global__ void gf_prep(const float* __restrict__ cw) {
    int idx = blockIdx.x * blockDim.x + threadIdx.x;
    if (idx < A14) {
        // 2*pi*idx/14 = pi * idx/7
        double frac = (double)idx / 7.0;
        g_cosT[idx] = (float)cospi(frac);
        g_sinT[idx] = (float)sinpi(frac);
    }
    if (idx >= NFREQ * A14 * CDIM) return;

    int c = idx % CDIM;
    int t = (idx / CDIM) % A14;
    int u = idx / (CDIM * A14);
    int u2 = (A14 - u) % A14;

    float kr = 0.f, ki = 0.f;
    float wr, wi, w2r, w2i;

    // v = 0 (DC): symmetrized, twiddle = 1
    {
        int b0 = ((u  * NFREQ + 0) * CDIM + c) * 2;
        int b1 = ((u2 * NFREQ + 0) * CDIM + c) * 2;
        wr = cw[b0]; wi = cw[b0 + 1];
        w2r = cw[b1]; w2i = cw[b1 + 1];
        kr += 0.5f * (wr + w2r);
        ki += 0.5f * (wi - w2i);
    }
    // v = 7 (Nyquist): symmetrized, twiddle = (-1)^t
    {
        int b0 = ((u  * NFREQ + 7) * CDIM + c) * 2;
        int b1 = ((u2 * NFREQ + 7) * CDIM + c) * 2;
        wr = cw[b0]; wi = cw[b0 + 1];
        w2r = cw[b1]; w2i = cw[b1 + 1];
        float sgn = (t & 1) ? -1.f : 1.f;
        kr += sgn * 0.5f * (wr + w2r);
        ki += sgn * 0.5f * (wi - w2i);
    }
    // v = 1..6: W[u,v]*w^{vt} + conj(W[u2,v])*w^{-vt}
    for (int v = 1; v <= 6; v++) {
        int m = (v * t) % A14;
        double frac = (double)m / 7.0;          // 2*pi*m/14 = pi*m/7
        float cc = (float)cospi(frac);
        float ss = (float)sinpi(frac);

        int b0 = ((u * NFREQ + v) * CDIM + c) * 2;
        wr = cw[b0]; wi = cw[b0 + 1];
        kr += wr * cc - wi * ss;
        ki += wr * ss + wi * cc;

        int b1 = ((u2 * NFREQ + v) * CDIM + c) * 2;
        w2r = cw[b1]; w2i = cw[b1 + 1];
        kr += w2r * cc - w2i * ss;
        ki -= w2r * ss + w2i * cc;
    }
    g_k[idx] = make_float2(kr * (1.f / 196.f), ki * (1.f / 196.f));
}

// ---------------------------------------------------------------------------
// Main kernel: one CTA = (batch b, 16-channel block). 128 threads = 16 ch x 8 u.
// ---------------------------------------------------------------------------
__global__ void __launch_bounds__(NTHREADS) gf_main(const float* __restrict__ x,
                                                    float* __restrict__ out) {
    __shared__ float xs[196 * CH];            // input tile / output staging
    __shared__ float qr[NFREQ * A14 * CH];    // Q real
    __shared__ float qi[NFREQ * A14 * CH];    // Q imag
    __shared__ float ct[A14], st[A14];

    int tid = threadIdx.x;
    int b = blockIdx.y;
    int c0 = blockIdx.x * CH;

    if (tid < A14) { ct[tid] = g_cosT[tid]; st[tid] = g_sinT[tid]; }

    // ---- cooperative coalesced load of x tile ----
    const float* xb = x + (size_t)b * 196 * CDIM + c0;
    #pragma unroll 4
    for (int i = tid; i < 196 * CH; i += NTHREADS) {
        int n = i / CH;
        int cl = i % CH;
        xs[i] = xb[n * CDIM + cl];
    }
    __syncthreads();

    int cl = tid & (CH - 1);
    int u  = tid >> 4;        // 0..7

    // ---- phase 1: Y[u][j] = sum_i x[i][j] * w^{-ui} ----
    float yr[A14], yi[A14];
    #pragma unroll
    for (int j = 0; j < A14; j++) { yr[j] = 0.f; yi[j] = 0.f; }
    #pragma unroll
    for (int i = 0; i < A14; i++) {
        int m = (u * i) % A14;
        float cc = ct[m], ss = st[m];
        #pragma unroll
        for (int j = 0; j < A14; j++) {
            float v = xs[(i * A14 + j) * CH + cl];
            yr[j] += v * cc;
            yi[j] -= v * ss;
        }
    }

    // ---- phase 1b: Q[u][j'] = sum_j Y[u][j] * k_u[(j'-j) mod 14] ----
    float2 kk[A14];
    #pragma unroll
    for (int t = 0; t < A14; t++)
        kk[t] = g_k[(u * A14 + t) * CDIM + (c0 + cl)];

    float pr[A14], pi_[A14];
    #pragma unroll
    for (int jp = 0; jp < A14; jp++) { pr[jp] = 0.f; pi_[jp] = 0.f; }
    #pragma unroll
    for (int j = 0; j < A14; j++) {
        float ar = yr[j], ai = yi[j];
        #pragma unroll
        for (int jp = 0; jp < A14; jp++) {
            int t = (jp - j + A14) % A14;   // compile-time constant (fully unrolled)
            float krv = kk[t].x, kiv = kk[t].y;
            pr[jp]  += ar * krv - ai * kiv;
            pi_[jp] += ar * kiv + ai * krv;
        }
    }
    #pragma unroll
    for (int jp = 0; jp < A14; jp++) {
        qr[(u * A14 + jp) * CH + cl] = pr[jp];
        qi[(u * A14 + jp) * CH + cl] = pi_[jp];
    }
    __syncthreads();

    // ---- phase 2: out[i][j] = Qr[0] + (-1)^i Qr[7] + 2*sum_{u=1..6}(cos Qr - sin Qi)
    // thread (cl, s) handles rows i0 = s, i1 = s+8 (when valid).
    {
        int i0 = u;
        int i1 = u + 8;
        float acc0[A14], acc1[A14];
        #pragma unroll
        for (int j = 0; j < A14; j++) { acc0[j] = 0.f; acc1[j] = 0.f; }

        #pragma unroll
        for (int uu = 0; uu < NFREQ; uu++) {
            float f = (uu == 0 || uu == 7) ? 1.f : 2.f;
            int m0 = (uu * i0) % A14;
            int m1 = (uu * i1) % A14;
            float c0c = f * ct[m0], s0c = f * st[m0];
            float c1c = f * ct[m1], s1c = f * st[m1];
            #pragma unroll
            for (int j = 0; j < A14; j++) {
                float qrv = qr[(uu * A14 + j) * CH + cl];
                float qiv = qi[(uu * A14 + j) * CH + cl];
                acc0[j] += c0c * qrv - s0c * qiv;
                acc1[j] += c1c * qrv - s1c * qiv;
            }
        }
        #pragma unroll
        for (int j = 0; j < A14; j++) {
            xs[(i0 * A14 + j) * CH + cl] = acc0[j];
            if (i1 < A14)
                xs[(i1 * A14 + j) * CH + cl] = acc1[j];
        }
    }
    __syncthreads();

    // ---- cooperative coalesced store ----
    float* ob = out + (size_t)b * 196 * CDIM + c0;
    #pragma unroll 4
    for (int i = tid; i < 196 * CH; i += NTHREADS) {
        int n = i / CH;
        int cc = i % CH;
        ob[n * CDIM + cc] = xs[i];
    }
}

extern "C" void kernel_launch(void* const* d_in, const int* in_sizes, int n_in,
                              void* d_out, int out_size) {
    const float* x  = (const float*)d_in[0];   // [256,196,768]
    const float* cw = (const float*)d_in[1];   // [14,8,768,2]
    float* out = (float*)d_out;                // [256,196,768]

    int prep_threads = NFREQ * A14 * CDIM;     // 86016
    gf_prep<<<(prep_threads + 255) / 256, 256>>>(cw);

    dim3 grid(CDIM / CH, BDIM);                // (48, 256)
    gf_main<<<grid, NTHREADS>>>(x, out);
}